// round 7
// baseline (speedup 1.0000x reference)
#include <cuda_runtime.h>

// out[b,k] = (WHT_2048(concat(x1[b],x2[b]))[k])^2 / 2048
// Two rows per thread packed as f32x2 (Blackwell packed fp32).
// Three layouts / two XOR-swizzled smem exchanges, coalesced LDG/STG.
// Persistent grid (148 SMs x 10 CTAs), grid-stride over row pairs.

#define THREADS 128
#define NPAIRS 4096
#define GRID 1480
typedef unsigned long long u64;

__device__ __forceinline__ u64 pack2(float a, float b) {
    u64 d; asm("mov.b64 %0,{%1,%2};" : "=l"(d) : "f"(a), "f"(b)); return d;
}
__device__ __forceinline__ void unpack2(u64 v, float& a, float& b) {
    asm("mov.b64 {%0,%1},%2;" : "=f"(a), "=f"(b) : "l"(v));
}
__device__ __forceinline__ u64 add2(u64 a, u64 b) {
    u64 d; asm("add.rn.f32x2 %0,%1,%2;" : "=l"(d) : "l"(a), "l"(b)); return d;
}
__device__ __forceinline__ u64 fma2(u64 a, u64 b, u64 c) {
    u64 d; asm("fma.rn.f32x2 %0,%1,%2,%3;" : "=l"(d) : "l"(a), "l"(b), "l"(c)); return d;
}
__device__ __forceinline__ u64 mul2(u64 a, u64 b) {
    u64 d; asm("mul.rn.f32x2 %0,%1,%2;" : "=l"(d) : "l"(a), "l"(b)); return d;
}

#define BFLY(x, y) do { u64 _s = add2(x, y); (y) = fma2(y, neg1, x); (x) = _s; } while (0)

__device__ __forceinline__ int swz(int j) { return j ^ ((j >> 4) & 15); }

__device__ __forceinline__ void wht16(u64* v, const u64 neg1) {
#pragma unroll
    for (int m = 1; m < 16; m <<= 1)
#pragma unroll
        for (int i = 0; i < 16; ++i)
            if ((i & m) == 0) BFLY(v[i], v[i | m]);
}

__global__ void __launch_bounds__(THREADS, 10) qf_wht_kernel(
    const float* __restrict__ x1,
    const float* __restrict__ x2,
    float* __restrict__ out)
{
    __shared__ __align__(16) u64 buf[2048];   // 16 KB, swizzled, no padding

    const int t = threadIdx.x;
    const u64 neg1 = 0xBF800000BF800000ULL;   // (-1.0f, -1.0f)
    const u64 scale2 = 0x3A0000003A000000ULL; // (1/2048, 1/2048)

    // row-invariant index math (hoisted out of the pair loop)
    const int tb = (t & 3) | ((t >> 2) << 6);             // layout B thread bits
    const int tc = ((t & 31) << 1) | ((t >> 5) << 9);     // layout C thread bits
    const size_t coff = (size_t)(4 * t);                  // load column offset

    for (int pair = blockIdx.x; pair < NPAIRS; pair += GRID) {
        const int rowA = pair * 2;
        const int rowB = rowA + 1;

        u64 v[16];

        // ---- coalesced load, layout A: v[k*4+c] = col (k*512 + 4t + c) ----
#pragma unroll
        for (int k = 0; k < 4; ++k) {
            const float* pa;
            const float* pb;
            if (k < 2) {
                pa = x1 + (size_t)rowA * 1024 + (size_t)k * 512 + coff;
                pb = x1 + (size_t)rowB * 1024 + (size_t)k * 512 + coff;
            } else {
                pa = x2 + (size_t)rowA * 1024 + (size_t)(k - 2) * 512 + coff;
                pb = x2 + (size_t)rowB * 1024 + (size_t)(k - 2) * 512 + coff;
            }
            float4 fa = *reinterpret_cast<const float4*>(pa);
            float4 fb = *reinterpret_cast<const float4*>(pb);
            v[k * 4 + 0] = pack2(fa.x, fb.x);
            v[k * 4 + 1] = pack2(fa.y, fb.y);
            v[k * 4 + 2] = pack2(fa.z, fb.z);
            v[k * 4 + 3] = pack2(fa.w, fb.w);
        }

        // ---- phase 1: bits 0,1 (c) and 9,10 (k) ----
        wht16(v, neg1);

        // ---- exchange 1: write layout A ----
#pragma unroll
        for (int k = 0; k < 4; ++k)
#pragma unroll
            for (int c = 0; c < 4; ++c)
                buf[swz(k * 512 + 4 * t + c)] = v[k * 4 + c];
        __syncthreads();

        // ---- read layout B: j = (i<<2) | tb ----
#pragma unroll
        for (int i = 0; i < 16; ++i)
            v[i] = buf[swz((i << 2) | tb)];

        // ---- phase 2: bits 2..5 ----
        wht16(v, neg1);

        // ---- exchange 2: write back to the SAME addresses ----
#pragma unroll
        for (int i = 0; i < 16; ++i)
            buf[swz((i << 2) | tb)] = v[i];
        __syncthreads();

        // ---- read layout C: j = (i&1) | tc | ((i>>1)<<6) ----
#pragma unroll
        for (int i = 0; i < 16; ++i)
            v[i] = buf[swz(tc | (i & 1) | ((i >> 1) << 6))];

        // ---- phase 3: bits 6..8 (WHT8 x2 copies) ----
#pragma unroll
        for (int m = 1; m < 8; m <<= 1)
#pragma unroll
            for (int h = 0; h < 2; ++h)
#pragma unroll
                for (int q = 0; q < 8; ++q)
                    if ((q & m) == 0) BFLY(v[q * 2 + h], v[(q | m) * 2 + h]);

        // ---- epilogue: square * 1/2048, coalesced float2 stores ----
        float* oA = out + (size_t)rowA * 2048;
        float* oB = out + (size_t)rowB * 2048;
#pragma unroll
        for (int p = 0; p < 8; ++p) {
            const int j0 = tc | (p << 6);
            u64 s0 = mul2(mul2(v[2 * p],     v[2 * p]),     scale2);
            u64 s1 = mul2(mul2(v[2 * p + 1], v[2 * p + 1]), scale2);
            float a0, b0, a1, b1;
            unpack2(s0, a0, b0);
            unpack2(s1, a1, b1);
            *reinterpret_cast<float2*>(oA + j0) = make_float2(a0, a1);
            *reinterpret_cast<float2*>(oB + j0) = make_float2(b0, b1);
        }

        __syncthreads();  // protect buf before next iteration's exchange-1
    }
}

extern "C" void kernel_launch(void* const* d_in, const int* in_sizes, int n_in,
                              void* d_out, int out_size)
{
    const float* x1 = (const float*)d_in[0];
    const float* x2 = (const float*)d_in[1];
    float* out = (float*)d_out;
    (void)in_sizes; (void)n_in; (void)out_size;

    qf_wht_kernel<<<GRID, THREADS>>>(x1, x2, out);
}

// round 8
// speedup vs baseline: 1.0349x; 1.0349x over previous
#include <cuda_runtime.h>

// out[b,k] = (WHT_2048(concat(x1[b],x2[b]))[k])^2 / 2048
// Two rows per thread packed as f32x2 (Blackwell packed fp32).
// Three layouts / two XOR-swizzled smem exchanges, coalesced LDG/STG.
// One CTA per row-pair (grid 4096), regs capped for 10 CTAs/SM.

#define THREADS 128
typedef unsigned long long u64;

__device__ __forceinline__ u64 pack2(float a, float b) {
    u64 d; asm("mov.b64 %0,{%1,%2};" : "=l"(d) : "f"(a), "f"(b)); return d;
}
__device__ __forceinline__ void unpack2(u64 v, float& a, float& b) {
    asm("mov.b64 {%0,%1},%2;" : "=f"(a), "=f"(b) : "l"(v));
}
__device__ __forceinline__ u64 add2(u64 a, u64 b) {
    u64 d; asm("add.rn.f32x2 %0,%1,%2;" : "=l"(d) : "l"(a), "l"(b)); return d;
}
__device__ __forceinline__ u64 fma2(u64 a, u64 b, u64 c) {
    u64 d; asm("fma.rn.f32x2 %0,%1,%2,%3;" : "=l"(d) : "l"(a), "l"(b), "l"(c)); return d;
}
__device__ __forceinline__ u64 mul2(u64 a, u64 b) {
    u64 d; asm("mul.rn.f32x2 %0,%1,%2;" : "=l"(d) : "l"(a), "l"(b)); return d;
}

#define BFLY(x, y) do { u64 _s = add2(x, y); (y) = fma2(y, neg1, x); (x) = _s; } while (0)

__device__ __forceinline__ int swz(int j) { return j ^ ((j >> 4) & 15); }

__device__ __forceinline__ void wht16(u64* v, const u64 neg1) {
#pragma unroll
    for (int m = 1; m < 16; m <<= 1)
#pragma unroll
        for (int i = 0; i < 16; ++i)
            if ((i & m) == 0) BFLY(v[i], v[i | m]);
}

__global__ void __launch_bounds__(THREADS, 10) qf_wht_kernel(
    const float* __restrict__ x1,
    const float* __restrict__ x2,
    float* __restrict__ out)
{
    __shared__ __align__(16) u64 buf[2048];   // 16 KB, swizzled, no padding

    const int t = threadIdx.x;
    const u64 neg1 = 0xBF800000BF800000ULL;   // (-1.0f, -1.0f)
    const u64 scale2 = 0x3A0000003A000000ULL; // (1/2048, 1/2048)

    const int rowA = blockIdx.x * 2;
    const int rowB = rowA + 1;

    u64 v[16];

    // ---- coalesced load, layout A: v[k*4+c] = col (k*512 + 4t + c) ----
    const size_t offA1 = (size_t)rowA * 1024 + 4 * t;
    const size_t offB1 = (size_t)rowB * 1024 + 4 * t;
#pragma unroll
    for (int k = 0; k < 4; ++k) {
        const float* pa = (k < 2) ? (x1 + offA1 + (size_t)k * 512)
                                  : (x2 + offA1 + (size_t)(k - 2) * 512);
        const float* pb = (k < 2) ? (x1 + offB1 + (size_t)k * 512)
                                  : (x2 + offB1 + (size_t)(k - 2) * 512);
        float4 fa = *reinterpret_cast<const float4*>(pa);
        float4 fb = *reinterpret_cast<const float4*>(pb);
        v[k * 4 + 0] = pack2(fa.x, fb.x);
        v[k * 4 + 1] = pack2(fa.y, fb.y);
        v[k * 4 + 2] = pack2(fa.z, fb.z);
        v[k * 4 + 3] = pack2(fa.w, fb.w);
    }

    // ---- phase 1: bits 0,1 (c) and 9,10 (k) ----
    wht16(v, neg1);

    // ---- exchange 1: write layout A ----
#pragma unroll
    for (int k = 0; k < 4; ++k)
#pragma unroll
        for (int c = 0; c < 4; ++c)
            buf[swz(k * 512 + 4 * t + c)] = v[k * 4 + c];
    __syncthreads();

    // ---- read layout B: j = (i<<2) | (t&3) | ((t>>2)<<6) ----
    const int tb = (t & 3) | ((t >> 2) << 6);
#pragma unroll
    for (int i = 0; i < 16; ++i)
        v[i] = buf[swz((i << 2) | tb)];

    // ---- phase 2: bits 2..5 ----
    wht16(v, neg1);

    // ---- exchange 2: write back to the SAME addresses ----
#pragma unroll
    for (int i = 0; i < 16; ++i)
        buf[swz((i << 2) | tb)] = v[i];
    __syncthreads();

    // ---- read layout C: j = (i&1) | ((t&31)<<1) | ((i>>1)<<6) | ((t>>5)<<9) ----
    const int tc = ((t & 31) << 1) | ((t >> 5) << 9);
#pragma unroll
    for (int i = 0; i < 16; ++i)
        v[i] = buf[swz(tc | (i & 1) | ((i >> 1) << 6))];

    // ---- phase 3: bits 6..8 (WHT8 x2 copies) ----
#pragma unroll
    for (int m = 1; m < 8; m <<= 1)
#pragma unroll
        for (int h = 0; h < 2; ++h)
#pragma unroll
            for (int q = 0; q < 8; ++q)
                if ((q & m) == 0) BFLY(v[q * 2 + h], v[(q | m) * 2 + h]);

    // ---- epilogue: square * 1/2048, coalesced float2 stores ----
    float* oA = out + (size_t)rowA * 2048;
    float* oB = out + (size_t)rowB * 2048;
#pragma unroll
    for (int p = 0; p < 8; ++p) {
        const int j0 = tc | (p << 6);
        u64 s0 = mul2(mul2(v[2 * p],     v[2 * p]),     scale2);
        u64 s1 = mul2(mul2(v[2 * p + 1], v[2 * p + 1]), scale2);
        float a0, b0, a1, b1;
        unpack2(s0, a0, b0);
        unpack2(s1, a1, b1);
        *reinterpret_cast<float2*>(oA + j0) = make_float2(a0, a1);
        *reinterpret_cast<float2*>(oB + j0) = make_float2(b0, b1);
    }
}

extern "C" void kernel_launch(void* const* d_in, const int* in_sizes, int n_in,
                              void* d_out, int out_size)
{
    const float* x1 = (const float*)d_in[0];
    const float* x2 = (const float*)d_in[1];
    float* out = (float*)d_out;
    (void)in_sizes; (void)n_in; (void)out_size;

    qf_wht_kernel<<<4096, THREADS>>>(x1, x2, out);
}

// round 9
// speedup vs baseline: 1.0957x; 1.0587x over previous
#include <cuda_runtime.h>

// out[b,k] = (WHT_2048(concat(x1[b],x2[b]))[k])^2 / 2048
// Two rows per thread packed as f32x2. Coalesced LDG/STG; two smem exchanges
// with PADDED affine addressing (p(j) = j + (j>>4)) -> conflict-free AND
// compile-time immediate LDS/STS offsets (no per-access swizzle ALU).

#define THREADS 128
typedef unsigned long long u64;

__device__ __forceinline__ u64 pack2(float a, float b) {
    u64 d; asm("mov.b64 %0,{%1,%2};" : "=l"(d) : "f"(a), "f"(b)); return d;
}
__device__ __forceinline__ void unpack2(u64 v, float& a, float& b) {
    asm("mov.b64 {%0,%1},%2;" : "=f"(a), "=f"(b) : "l"(v));
}
__device__ __forceinline__ u64 add2(u64 a, u64 b) {
    u64 d; asm("add.rn.f32x2 %0,%1,%2;" : "=l"(d) : "l"(a), "l"(b)); return d;
}
__device__ __forceinline__ u64 fma2(u64 a, u64 b, u64 c) {
    u64 d; asm("fma.rn.f32x2 %0,%1,%2,%3;" : "=l"(d) : "l"(a), "l"(b), "l"(c)); return d;
}
__device__ __forceinline__ u64 mul2(u64 a, u64 b) {
    u64 d; asm("mul.rn.f32x2 %0,%1,%2;" : "=l"(d) : "l"(a), "l"(b)); return d;
}

#define BFLY(x, y) do { u64 _s = add2(x, y); (y) = fma2(y, neg1, x); (x) = _s; } while (0)

__device__ __forceinline__ void wht16(u64* v, const u64 neg1) {
#pragma unroll
    for (int m = 1; m < 16; m <<= 1)
#pragma unroll
        for (int i = 0; i < 16; ++i)
            if ((i & m) == 0) BFLY(v[i], v[i | m]);
}

__global__ void __launch_bounds__(THREADS) qf_wht_kernel(
    const float* __restrict__ x1,
    const float* __restrict__ x2,
    float* __restrict__ out)
{
    __shared__ __align__(16) u64 buf[2176];   // 2048 + 128 pad = 17408 B

    const int t = threadIdx.x;
    const u64 neg1   = 0xBF800000BF800000ULL; // (-1.0f, -1.0f)
    const u64 scale2 = 0x3A0000003A000000ULL; // (1/2048, 1/2048)

    const int rowA = blockIdx.x * 2;
    const int rowB = rowA + 1;

    u64 v[16];

    // ---- coalesced load, layout A: v[k*4+c] = col (k*512 + 4t + c) ----
    const size_t offA1 = (size_t)rowA * 1024 + 4 * t;
    const size_t offB1 = (size_t)rowB * 1024 + 4 * t;
#pragma unroll
    for (int k = 0; k < 4; ++k) {
        const float* pa = (k < 2) ? (x1 + offA1 + (size_t)k * 512)
                                  : (x2 + offA1 + (size_t)(k - 2) * 512);
        const float* pb = (k < 2) ? (x1 + offB1 + (size_t)k * 512)
                                  : (x2 + offB1 + (size_t)(k - 2) * 512);
        float4 fa = *reinterpret_cast<const float4*>(pa);
        float4 fb = *reinterpret_cast<const float4*>(pb);
        v[k * 4 + 0] = pack2(fa.x, fb.x);
        v[k * 4 + 1] = pack2(fa.y, fb.y);
        v[k * 4 + 2] = pack2(fa.z, fb.z);
        v[k * 4 + 3] = pack2(fa.w, fb.w);
    }

    // ---- phase 1: bits 0,1 (c) and 9,10 (k) ----
    wht16(v, neg1);

    // ---- exchange 1 write, layout A: addr = 544k + c + [4t + (t>>2)] ----
    {
        u64* pA = buf + 4 * t + (t >> 2);
#pragma unroll
        for (int k = 0; k < 4; ++k)
#pragma unroll
            for (int c = 0; c < 4; ++c)
                pA[544 * k + c] = v[k * 4 + c];
    }
    __syncthreads();

    // ---- read layout B: j = (i<<2)|(t&3)|((t>>2)<<6)
    //      addr = [ (t&3) + 68*(t>>2) ] + 4i + (i>>2) ----
    u64* pB = buf + (t & 3) + 68 * (t >> 2);
#pragma unroll
    for (int i = 0; i < 16; ++i)
        v[i] = pB[4 * i + (i >> 2)];

    // ---- phase 2: bits 2..5 ----
    wht16(v, neg1);

    // ---- exchange 2: write back to the SAME addresses ----
#pragma unroll
    for (int i = 0; i < 16; ++i)
        pB[4 * i + (i >> 2)] = v[i];
    __syncthreads();

    // ---- read layout C: j = (i&1)|((t&31)<<1)|((i>>1)<<6)|((t>>5)<<9)
    //      addr = [ 2(t&31) + ((t>>3)&3) + 544(t>>5) ] + (i&1) + 68*(i>>1) ----
    u64* pC = buf + 2 * (t & 31) + ((t >> 3) & 3) + 544 * (t >> 5);
#pragma unroll
    for (int i = 0; i < 16; ++i)
        v[i] = pC[(i & 1) + 68 * (i >> 1)];

    // ---- phase 3: bits 6..8 (WHT8 x2 copies) ----
#pragma unroll
    for (int m = 1; m < 8; m <<= 1)
#pragma unroll
        for (int h = 0; h < 2; ++h)
#pragma unroll
            for (int q = 0; q < 8; ++q)
                if ((q & m) == 0) BFLY(v[q * 2 + h], v[(q | m) * 2 + h]);

    // ---- epilogue: square * 1/2048, coalesced float2 stores ----
    const int tc = ((t & 31) << 1) | ((t >> 5) << 9);
    float* oA = out + (size_t)rowA * 2048;
    float* oB = out + (size_t)rowB * 2048;
#pragma unroll
    for (int p = 0; p < 8; ++p) {
        const int j0 = tc | (p << 6);
        u64 s0 = mul2(mul2(v[2 * p],     v[2 * p]),     scale2);
        u64 s1 = mul2(mul2(v[2 * p + 1], v[2 * p + 1]), scale2);
        float a0, b0, a1, b1;
        unpack2(s0, a0, b0);
        unpack2(s1, a1, b1);
        *reinterpret_cast<float2*>(oA + j0) = make_float2(a0, a1);
        *reinterpret_cast<float2*>(oB + j0) = make_float2(b0, b1);
    }
}

extern "C" void kernel_launch(void* const* d_in, const int* in_sizes, int n_in,
                              void* d_out, int out_size)
{
    const float* x1 = (const float*)d_in[0];
    const float* x2 = (const float*)d_in[1];
    float* out = (float*)d_out;
    (void)in_sizes; (void)n_in; (void)out_size;

    qf_wht_kernel<<<4096, THREADS>>>(x1, x2, out);
}